// round 11
// baseline (speedup 1.0000x reference)
#include <cuda_runtime.h>
#include <cuda_bf16.h>
#include <stdint.h>

#define LOG2E 1.4426950408889634f
#define MAXBLK 160

__device__ float g_part[MAXBLK * 8192];

__device__ __forceinline__ uint32_t smem_u32(const void* p) {
    uint32_t a;
    asm("{ .reg .u64 t; cvta.to.shared.u64 t, %1; cvt.u32.u64 %0, t; }" : "=r"(a) : "l"(p));
    return a;
}
__device__ __forceinline__ float ex2f(float x) {
    float r; asm("ex2.approx.ftz.f32 %0, %1;" : "=f"(r) : "f"(x)); return r;
}
__device__ __forceinline__ uint32_t swz(uint32_t o) { return o ^ ((o >> 3) & 0x70u); }

__device__ __forceinline__ void ldm4(uint32_t a, uint32_t& r0, uint32_t& r1, uint32_t& r2, uint32_t& r3) {
    asm volatile("ldmatrix.sync.aligned.m8n8.x4.shared.b16 {%0,%1,%2,%3}, [%4];"
                 : "=r"(r0), "=r"(r1), "=r"(r2), "=r"(r3) : "r"(a));
}
__device__ __forceinline__ void ldm4t(uint32_t a, uint32_t& r0, uint32_t& r1, uint32_t& r2, uint32_t& r3) {
    asm volatile("ldmatrix.sync.aligned.m8n8.x4.trans.shared.b16 {%0,%1,%2,%3}, [%4];"
                 : "=r"(r0), "=r"(r1), "=r"(r2), "=r"(r3) : "r"(a));
}
__device__ __forceinline__ void mma16816(float* d, const uint32_t* a, uint32_t b0, uint32_t b1) {
    asm volatile("mma.sync.aligned.m16n8k16.row.col.f32.bf16.bf16.f32 "
                 "{%0,%1,%2,%3}, {%4,%5,%6,%7}, {%8,%9}, {%0,%1,%2,%3};"
                 : "+f"(d[0]), "+f"(d[1]), "+f"(d[2]), "+f"(d[3])
                 : "r"(a[0]), "r"(a[1]), "r"(a[2]), "r"(a[3]), "r"(b0), "r"(b1));
}

// packed split: hi = bf16x2(v1|v0), lo = bf16x2 of exact residuals
__device__ __forceinline__ void split2(float v0, float v1, uint32_t& hi, uint32_t& lo) {
    uint32_t h;
    asm("cvt.rn.bf16x2.f32 %0, %1, %2;" : "=r"(h) : "f"(v1), "f"(v0));
    float h0 = __uint_as_float(h << 16);
    float h1 = __uint_as_float(h & 0xffff0000u);
    float r0 = v0 - h0, r1 = v1 - h1;
    asm("cvt.rn.bf16x2.f32 %0, %1, %2;" : "=r"(lo) : "f"(r1), "f"(r0));
    hi = h;
}

__device__ __forceinline__ void store_split(char* dh, char* dl, int row, int half, const float4* v) {
    uint32_t base = (uint32_t)row * 128u + (uint32_t)half * 64u;
#pragma unroll
    for (int j = 0; j < 8; j++) {
        float4 f = v[j];
        uint32_t h0, l0, h1, l1;
        split2(f.x, f.y, h0, l0);
        split2(f.z, f.w, h1, l1);
        uint32_t so = swz(base + (uint32_t)j * 8u);
        *reinterpret_cast<uint2*>(dh + so) = make_uint2(h0, h1);
        *reinterpret_cast<uint2*>(dl + so) = make_uint2(l0, l1);
    }
}

__global__ void __launch_bounds__(256, 1)
hist_kernel(const float* __restrict__ x, const float* __restrict__ cen, int ntiles) {
    __shared__ alignas(128) char stile[32768];  // [0,16K) hi tile, [16K,32K) lo tile
    __shared__ float hx2s[128];                 // 0.5*|x_n|^2*log2e
    __shared__ float hc2s[128];                 // 0.5*|c_o|^2*log2e

    char* sxh = stile;
    char* sxl = stile + 16384;
    const int tid = threadIdx.x, wid = tid >> 5, lane = tid & 31;
    const int g = lane >> 2, t = lane & 3;
    const uint32_t xh_b = smem_u32(sxh), xl_b = smem_u32(sxl);
    const uint32_t lm = (uint32_t)(lane >> 3), lr = (uint32_t)(lane & 7);
    const int og = wid & 3;                          // o-group: rows og*32..og*32+31
    const uint32_t nh = (uint32_t)(wid >> 2) * 64u;  // n-half: rows nh..nh+63

    // center norms (prescaled)
    if (tid < 128) {
        const float4* p = reinterpret_cast<const float4*>(cen + (size_t)tid * 64);
        float s = 0.f;
#pragma unroll
        for (int j = 0; j < 16; j++) {
            float4 f = p[j];
            s += f.x * f.x + f.y * f.y + f.z * f.z + f.w * f.w;
        }
        hc2s[tid] = 0.5f * LOG2E * s;
    }

    // center A-fragments: 2 o-blocks (16 rows each) x 4 k-chunks, resident in regs
    uint32_t ch[2][4][4], cl[2][4][4];
#pragma unroll
    for (int ob = 0; ob < 2; ob++) {
        const int o0 = og * 32 + ob * 16 + g;
#pragma unroll
        for (int k = 0; k < 4; k++) {
            const float* b0 = cen + (size_t)o0 * 64 + 16 * k + 2 * t;
            const float* b1 = cen + (size_t)(o0 + 8) * 64 + 16 * k + 2 * t;
            float2 f0 = *reinterpret_cast<const float2*>(b0);
            float2 f1 = *reinterpret_cast<const float2*>(b1);
            float2 f2 = *reinterpret_cast<const float2*>(b0 + 8);
            float2 f3 = *reinterpret_cast<const float2*>(b1 + 8);
            split2(f0.x, f0.y, ch[ob][k][0], cl[ob][k][0]);
            split2(f1.x, f1.y, ch[ob][k][1], cl[ob][k][1]);
            split2(f2.x, f2.y, ch[ob][k][2], cl[ob][k][2]);
            split2(f3.x, f3.y, ch[ob][k][3], cl[ob][k][3]);
        }
    }
    __syncthreads();
    const float hc0A = hc2s[og * 32 + g],      hc0B = hc2s[og * 32 + 8 + g];
    const float hc1A = hc2s[og * 32 + 16 + g], hc1B = hc2s[og * 32 + 24 + g];

    float acc2[16][4];  // hist partial: 32(o) x 64(i), this warp's n-half only
#pragma unroll
    for (int i = 0; i < 16; i++)
#pragma unroll
        for (int q = 0; q < 4; q++) acc2[i][q] = 0.f;

    for (int tile = blockIdx.x; tile < ntiles; tile += gridDim.x) {
        // ---- stage x tile (LDGs before barrier overlap prior GEMM2) ----
        const int r = tid >> 1, half = tid & 1;
        const float4* p = reinterpret_cast<const float4*>(
            x + (size_t)(tile * 128 + r) * 64 + half * 32);
        float4 v[8];
#pragma unroll
        for (int j = 0; j < 8; j++) v[j] = p[j];
        __syncthreads();
        float ss = 0.f;
#pragma unroll
        for (int j = 0; j < 8; j++)
            ss += v[j].x * v[j].x + v[j].y * v[j].y + v[j].z * v[j].z + v[j].w * v[j].w;
        float tot = ss + __shfl_xor_sync(0xFFFFFFFFu, ss, 1);
        if (half == 0) hx2s[r] = 0.5f * LOG2E * tot;
        store_split(sxh, sxl, r, half, v);
        __syncthreads();

        // ---- GEMM1: S[32o x 64n] = C . X^T (split-bf16, 3 passes) ----
        float acc1[16][4];
#pragma unroll
        for (int i = 0; i < 16; i++)
#pragma unroll
            for (int q = 0; q < 4; q++) acc1[i][q] = 0.f;
#pragma unroll
        for (int jp = 0; jp < 4; jp++) {
#pragma unroll
            for (int k = 0; k < 4; k++) {
                uint32_t off = (nh + 16u * jp + (lm >> 1) * 8u + lr) * 128u + 32u * k + (lm & 1u) * 16u;
                uint32_t h0, h1, h2, h3, l0, l1, l2, l3;
                ldm4(xh_b + swz(off), h0, h1, h2, h3);
                ldm4(xl_b + swz(off), l0, l1, l2, l3);
#pragma unroll
                for (int ob = 0; ob < 2; ob++) {
                    float* aA = acc1[ob * 8 + 2 * jp];
                    float* aB = acc1[ob * 8 + 2 * jp + 1];
                    mma16816(aA, ch[ob][k], h0, h1);
                    mma16816(aA, ch[ob][k], l0, l1);
                    mma16816(aA, cl[ob][k], h0, h1);
                    mma16816(aB, ch[ob][k], h2, h3);
                    mma16816(aB, ch[ob][k], l2, l3);
                    mma16816(aB, cl[ob][k], h2, h3);
                }
            }
        }

        // ---- epilogue (rbf in regs, C->A fragment reuse) + GEMM2 interleaved ----
#pragma unroll
        for (int kk = 0; kk < 4; kk++) {
            float2 hxa = *reinterpret_cast<const float2*>(&hx2s[nh + 16u * kk + 2 * t]);
            float2 hxb = *reinterpret_cast<const float2*>(&hx2s[nh + 16u * kk + 8 + 2 * t]);
            uint32_t ah[2][4], al[2][4];
#pragma unroll
            for (int ob = 0; ob < 2; ob++) {
                const int j0 = ob * 8 + 2 * kk, j1 = j0 + 1;
                const float hA = ob ? hc1A : hc0A;
                const float hB = ob ? hc1B : hc0B;
                float v00 = ex2f(fmaf(acc1[j0][0], LOG2E, -hA) - hxa.x);
                float v01 = ex2f(fmaf(acc1[j0][1], LOG2E, -hA) - hxa.y);
                float v02 = ex2f(fmaf(acc1[j0][2], LOG2E, -hB) - hxa.x);
                float v03 = ex2f(fmaf(acc1[j0][3], LOG2E, -hB) - hxa.y);
                float v10 = ex2f(fmaf(acc1[j1][0], LOG2E, -hA) - hxb.x);
                float v11 = ex2f(fmaf(acc1[j1][1], LOG2E, -hA) - hxb.y);
                float v12 = ex2f(fmaf(acc1[j1][2], LOG2E, -hB) - hxb.x);
                float v13 = ex2f(fmaf(acc1[j1][3], LOG2E, -hB) - hxb.y);
                split2(v00, v01, ah[ob][0], al[ob][0]);
                split2(v02, v03, ah[ob][1], al[ob][1]);
                split2(v10, v11, ah[ob][2], al[ob][2]);
                split2(v12, v13, ah[ob][3], al[ob][3]);
            }
#pragma unroll
            for (int ip = 0; ip < 4; ip++) {
                uint32_t off = (nh + 16u * kk + (lm & 1u) * 8u + lr) * 128u + 32u * ip + (lm >> 1) * 16u;
                uint32_t h0, h1, h2, h3, l0, l1, l2, l3;
                ldm4t(xh_b + swz(off), h0, h1, h2, h3);
                ldm4t(xl_b + swz(off), l0, l1, l2, l3);
#pragma unroll
                for (int ob = 0; ob < 2; ob++) {
                    float* aA = acc2[ob * 8 + 2 * ip];
                    float* aB = acc2[ob * 8 + 2 * ip + 1];
                    mma16816(aA, ah[ob], h0, h1);
                    mma16816(aA, ah[ob], l0, l1);
                    mma16816(aA, al[ob], h0, h1);
                    mma16816(aB, ah[ob], h2, h3);
                    mma16816(aB, ah[ob], l2, l3);
                    mma16816(aB, al[ob], h2, h3);
                }
            }
        }
    }

    // ---- combine n-halves (fixed order -> deterministic) and write partials ----
    __syncthreads();  // all warps done reading stile
    float* comb = reinterpret_cast<float*>(stile);
    if (wid >= 4) {
        float* d = comb + (size_t)(wid - 4) * 2048 + (size_t)lane * 64;
#pragma unroll
        for (int i = 0; i < 16; i++)
            *reinterpret_cast<float4*>(d + 4 * i) =
                make_float4(acc2[i][0], acc2[i][1], acc2[i][2], acc2[i][3]);
    }
    __syncthreads();
    if (wid < 4) {
        const float* s = comb + (size_t)wid * 2048 + (size_t)lane * 64;
#pragma unroll
        for (int i = 0; i < 16; i++) {
            float4 f = *reinterpret_cast<const float4*>(s + 4 * i);
            acc2[i][0] += f.x; acc2[i][1] += f.y; acc2[i][2] += f.z; acc2[i][3] += f.w;
        }
        float* dst = g_part + (size_t)blockIdx.x * 8192;
#pragma unroll
        for (int ob = 0; ob < 2; ob++) {
            const int o = og * 32 + ob * 16 + g;
#pragma unroll
            for (int ib = 0; ib < 8; ib++) {
                *reinterpret_cast<float2*>(dst + (size_t)o * 64 + 8 * ib + 2 * t) =
                    make_float2(acc2[ob * 8 + ib][0], acc2[ob * 8 + ib][1]);
                *reinterpret_cast<float2*>(dst + (size_t)(o + 8) * 64 + 8 * ib + 2 * t) =
                    make_float2(acc2[ob * 8 + ib][2], acc2[ob * 8 + ib][3]);
            }
        }
    }
}

// 512 blocks x 256 thr: block owns 16 outputs; 16 chunks per output; fixed-order combine.
__global__ void reduce_kernel(float* __restrict__ out, int nblk) {
    __shared__ float red[256];
    const int ol = threadIdx.x & 15;
    const int o = blockIdx.x * 16 + ol;
    const int chunk = threadIdx.x >> 4;
    const int per = (nblk + 15) >> 4;
    const int b0 = chunk * per;
    const int b1 = (b0 + per < nblk) ? (b0 + per) : nblk;
    float s = 0.f;
    for (int b = b0; b < b1; b++) s += g_part[(size_t)b * 8192 + o];
    red[threadIdx.x] = s;
    __syncthreads();
    if (threadIdx.x < 16) {
        float ts = red[ol];
#pragma unroll
        for (int c = 1; c < 16; c++) ts += red[c * 16 + ol];
        out[o] = ts;
    }
}

extern "C" void kernel_launch(void* const* d_in, const int* in_sizes, int n_in,
                              void* d_out, int out_size) {
    const float* x = (const float*)d_in[0];
    const float* c = (const float*)d_in[1];
    int N = in_sizes[0] / 64;
    int ntiles = N / 128;
    int dev = 0, sm = 0, nblk = 148;
    if (cudaGetDevice(&dev) == cudaSuccess &&
        cudaDeviceGetAttribute(&sm, cudaDevAttrMultiProcessorCount, dev) == cudaSuccess &&
        sm > 0) {
        nblk = sm > MAXBLK ? MAXBLK : sm;
    }
    if (nblk > ntiles) nblk = ntiles;
    hist_kernel<<<nblk, 256>>>(x, c, ntiles);
    reduce_kernel<<<512, 256>>>((float*)d_out, nblk);
}